// round 8
// baseline (speedup 1.0000x reference)
#include <cuda_runtime.h>
#include <stdint.h>

// Problem: B=64, C=256, H=64, W=64, k=8.  out: [64, 8, 259] fp32
#define BB   64
#define CC   256
#define HH   64
#define WW   64
#define NPB  (1 << 20)          // elements per batch (C*H*W)
#define KK   8
#define OUTC (CC + 3)           // 259
#define CAP  16384              // candidate capacity per batch

#define CH     16               // filter chunks per batch
#define CHUNK  (NPB / CH)       // 65536 elements
#define TPB    256
#define GROUPS 8                // per-thread groups in filter (8*32 = 256 elem/thread)

#define TSL      4              // threshold slices per batch
#define SLICE_E  16384          // elements sampled per slice
#define TPB_T    256

typedef unsigned long long u64;
typedef unsigned int u32;

__device__ u64 g_cand[BB * CAP];     // 8 MB scratch (static, allocation-free)
__device__ int g_count[BB];
__device__ int g_done[BB];
__device__ u32 g_tmono[BB * TSL];    // per-slice partial thresholds (monotonic)

// monotonic float<->uint mapping (total order matches float compare)
__device__ __forceinline__ u32 f2mono(float f) {
    u32 b = __float_as_uint(f);
    return b ^ ((u32)((int)b >> 31) | 0x80000000u);
}
__device__ __forceinline__ float mono2f(u32 m) {
    u32 b = (m & 0x80000000u) ? (m ^ 0x80000000u) : ~m;
    return __uint_as_float(b);
}
__device__ __forceinline__ u64 make_key(float v, u32 idx) {
    return ((u64)f2mono(v) << 32) | (u32)(~idx);
}

// exact top-8 insert by key (value desc, index asc) — matches lax.top_k
__device__ __forceinline__ void consider_key(u64 (&top)[KK], u64 key) {
    if (key > top[KK - 1]) {
        top[KK - 1] = key;
        #pragma unroll
        for (int j = KK - 1; j > 0; --j) {
            if (top[j] > top[j - 1]) { u64 t = top[j]; top[j] = top[j - 1]; top[j - 1] = t; }
        }
    }
}

// ─────── Pass A: parallel threshold — each block: min of 8 group maxes ───────
// grid (BB, TSL). Block (b,s) samples elements [s*SLICE_E, (s+1)*SLICE_E) of
// batch b, partitioned into 8 disjoint groups by (tid & 7). Final threshold
// (combined in the filter) = min over all TSL*8 = 32 disjoint group maxes →
// at least 32 distinct positions >= T → T <= true 8th-largest. Never drops a
// true top-8 element, for any input.
__global__ __launch_bounds__(TPB_T)
void k_thresh(const float* __restrict__ x) {
    const int b = blockIdx.x;
    const int s = blockIdx.y;
    const int tid = threadIdx.x;
    if (s == 0 && tid == 0) { g_count[b] = 0; g_done[b] = 0; }

    const float4* __restrict__ p =
        (const float4*)(x + (size_t)b * NPB + (size_t)s * SLICE_E);
    const float NEG_INF = -__int_as_float(0x7f800000);

    float m0 = NEG_INF, m1 = NEG_INF, m2 = NEG_INF, m3 = NEG_INF;
    #pragma unroll
    for (int i = 0; i < SLICE_E / (TPB_T * 4); ++i) {   // 16 float4/thread
        float4 v = p[i * TPB_T + tid];
        m0 = fmaxf(m0, v.x); m1 = fmaxf(m1, v.y);
        m2 = fmaxf(m2, v.z); m3 = fmaxf(m3, v.w);
    }
    float m = fmaxf(fmaxf(m0, m1), fmaxf(m2, m3));

    // group = tid & 7: lanes g, g+8, g+16, g+24 share a group within a warp
    m = fmaxf(m, __shfl_xor_sync(0xFFFFFFFFu, m, 8));
    m = fmaxf(m, __shfl_xor_sync(0xFFFFFFFFu, m, 16));

    __shared__ float gsm[(TPB_T / 32) * 8];
    const int lane = tid & 31, warp = tid >> 5;
    if (lane < 8) gsm[warp * 8 + lane] = m;
    __syncthreads();

    if (tid < 8) {
        float gm = NEG_INF;
        #pragma unroll
        for (int w = 0; w < TPB_T / 32; ++w)
            gm = fmaxf(gm, gsm[w * 8 + tid]);
        float mn = gm;                       // min over the 8 group maxes
        #pragma unroll
        for (int off = 4; off > 0; off >>= 1)
            mn = fminf(mn, __shfl_xor_sync(0x000000FFu, mn, off));
        if (tid == 0) g_tmono[b * TSL + s] = f2mono(mn);
    }
}

// ───────────── selection (runs inside the last filter block per batch) ──────
// Reader side of the release/acquire pair: g_cand / g_count reads go through
// __ldcg (L2) so they cannot hit stale L1 lines; writers published with
// st → __threadfence → __syncthreads → atomicAdd(done).
__device__ void do_select(int b, const float* __restrict__ x,
                          float* __restrict__ out) {
    const int tid = threadIdx.x;
    const int cnt = __ldcg(&g_count[b]);

    u64 top[KK];
    #pragma unroll
    for (int j = 0; j < KK; ++j) top[j] = 0ull;

    if (cnt >= KK && cnt <= CAP) {
        for (int i = tid; i < cnt; i += TPB)
            consider_key(top, __ldcg(&g_cand[b * CAP + i]));
    } else {
        // fallback: exact brute-force scan of the whole batch (cold path)
        const float4* __restrict__ p = (const float4*)(x + (size_t)b * NPB);
        for (int i = tid; i < NPB / 4; i += TPB) {
            float4 v = p[i];
            u32 e = (u32)i * 4u;
            consider_key(top, make_key(v.x, e + 0u));
            consider_key(top, make_key(v.y, e + 1u));
            consider_key(top, make_key(v.z, e + 2u));
            consider_key(top, make_key(v.w, e + 3u));
        }
    }

    __shared__ u64 cand[TPB * KK];
    __shared__ u64 wmax[TPB / 32];
    __shared__ u64 winner;
    __shared__ u64 topk[KK];
    #pragma unroll
    for (int j = 0; j < KK; ++j) cand[tid * KK + j] = top[j];
    __syncthreads();

    const int lane = tid & 31, warp = tid >> 5;
    for (int sel = 0; sel < KK; ++sel) {
        u64 m = 0ull;
        #pragma unroll
        for (int j = 0; j < KK; ++j) { u64 cc = cand[tid * KK + j]; if (cc > m) m = cc; }
        #pragma unroll
        for (int off = 16; off > 0; off >>= 1) {
            u64 o = __shfl_down_sync(0xFFFFFFFFu, m, off);
            if (o > m) m = o;
        }
        if (lane == 0) wmax[warp] = m;
        __syncthreads();
        if (tid == 0) {
            u64 w = 0ull;
            #pragma unroll
            for (int q = 0; q < TPB / 32; ++q) if (wmax[q] > w) w = wmax[q];
            winner = w;
            topk[sel] = w;
        }
        __syncthreads();
        u64 w = winner;
        #pragma unroll
        for (int j = 0; j < KK; ++j)
            if (cand[tid * KK + j] == w) cand[tid * KK + j] = 0ull;
        __syncthreads();
    }

    float* ob = out + (size_t)b * KK * OUTC;
    for (int i = tid; i < KK * OUTC; i += TPB) ob[i] = 0.0f;
    __syncthreads();

    if (tid < KK) {
        u64 k = topk[tid];
        float val = mono2f((u32)(k >> 32));
        u32 idx = ~((u32)k);
        int ci  = (int)(idx >> 12);
        int rem = (int)(idx & 4095u);
        int y   = rem >> 6;
        int xq  = rem & 63;
        float* row = ob + tid * OUTC;
        row[ci]     = 1.0f;
        row[CC + 0] = val;
        row[CC + 1] = (float)xq * (1.0f / (WW - 1));
        row[CC + 2] = (float)y  * (1.0f / (HH - 1));
    }
}

// ───────────── Pass B: stream + filter + compact (+ fused select) ───────────
__device__ __forceinline__ void emit(int b, float v, u32 idx) {
    int s = atomicAdd(&g_count[b], 1);
    if (s < CAP) g_cand[b * CAP + s] = make_key(v, idx);
}

__global__ __launch_bounds__(TPB)
void k_filter(const float* __restrict__ x, float* __restrict__ out) {
    const int c = blockIdx.x;
    const int b = blockIdx.y;
    const int tid = threadIdx.x;

    // combine partial thresholds (monotonic min over TSL slices)
    u32 tm = g_tmono[b * TSL + 0];
    #pragma unroll
    for (int s = 1; s < TSL; ++s) tm = umin(tm, g_tmono[b * TSL + s]);
    const float TF = mono2f(tm);
    const u32 TB = (tm >= 0x80000000u) ? (tm ^ 0x80000000u) : 0u;

    const u32 cbase = (u32)c * CHUNK;
    const uint4* __restrict__ p = (const uint4*)(x + (size_t)b * NPB + cbase);

    #pragma unroll 4
    for (int i = 0; i < GROUPS; ++i) {
        uint4 q[8];
        #pragma unroll
        for (int j = 0; j < 8; ++j)
            q[j] = __ldcs(&p[(i * 8 + j) * TPB + tid]);   // streaming, no reuse

        // DPX 3-input unsigned max tree: 32 values -> 1 in 16 ops.
        // Unsigned bit compare is exact for non-negative floats; negatives/NaN
        // compare high -> false positives only (rechecked exactly below).
        u32 s0 = __vimax3_u32(q[0].x, q[0].y, q[0].z);
        u32 s1 = __vimax3_u32(q[1].x, q[1].y, q[1].z);
        u32 s2 = __vimax3_u32(q[2].x, q[2].y, q[2].z);
        u32 s3 = __vimax3_u32(q[3].x, q[3].y, q[3].z);
        u32 s4 = __vimax3_u32(q[4].x, q[4].y, q[4].z);
        u32 s5 = __vimax3_u32(q[5].x, q[5].y, q[5].z);
        u32 s6 = __vimax3_u32(q[6].x, q[6].y, q[6].z);
        u32 s7 = __vimax3_u32(q[7].x, q[7].y, q[7].z);
        u32 u0 = __vimax3_u32(s0, s1, q[0].w);
        u32 u1 = __vimax3_u32(s2, s3, q[1].w);
        u32 u2 = __vimax3_u32(s4, s5, q[2].w);
        u32 u3 = __vimax3_u32(s6, s7, q[3].w);
        u32 v0 = __vimax3_u32(u0, u1, q[4].w);
        u32 v1 = __vimax3_u32(u2, u3, q[5].w);
        u32 mm = __vimax3_u32(v0, v1, q[6].w);
        mm     = __vimax3_u32(mm, q[7].w, 0u);

        if (mm >= TB) {
            #pragma unroll
            for (int j = 0; j < 8; ++j) {
                u32 e = cbase + ((u32)(i * 8 + j) * TPB + (u32)tid) * 4u;
                float v0f = __uint_as_float(q[j].x);
                float v1f = __uint_as_float(q[j].y);
                float v2f = __uint_as_float(q[j].z);
                float v3f = __uint_as_float(q[j].w);
                if (v0f >= TF) emit(b, v0f, e + 0u);
                if (v1f >= TF) emit(b, v1f, e + 1u);
                if (v2f >= TF) emit(b, v2f, e + 2u);
                if (v3f >= TF) emit(b, v3f, e + 3u);
            }
        }
    }

    // fused select, threadFenceReduction pattern:
    //   per-thread: stores → __threadfence (device-visible)
    //   __syncthreads: ALL threads' fences complete before tid0's atomic
    //   tid0: atomicAdd(done)  — the release is now block-wide
    __threadfence();
    __syncthreads();
    __shared__ int is_last;
    if (tid == 0) is_last = (atomicAdd(&g_done[b], 1) == CH - 1) ? 1 : 0;
    __syncthreads();
    if (is_last) {
        __threadfence();          // acquire: order candidate reads after the
                                  // observed done-count
        do_select(b, x, out);
    }
}

extern "C" void kernel_launch(void* const* d_in, const int* in_sizes, int n_in,
                              void* d_out, int out_size) {
    const float* x = (const float*)d_in[0];
    float* out = (float*)d_out;

    dim3 gt(BB, TSL);
    k_thresh<<<gt, TPB_T>>>(x);
    dim3 gf(CH, BB);
    k_filter<<<gf, TPB>>>(x, out);
}

// round 9
// speedup vs baseline: 1.8879x; 1.8879x over previous
#include <cuda_runtime.h>
#include <stdint.h>

// Problem: B=64, C=256, H=64, W=64, k=8.  out: [64, 8, 259] fp32
#define BB   64
#define CC   256
#define HH   64
#define WW   64
#define NPB  (1 << 20)          // elements per batch (C*H*W)
#define KK   8
#define OUTC (CC + 3)           // 259
#define CAP  16384              // candidate capacity per batch

#define CH     16               // filter chunks per batch
#define CHUNK  (NPB / CH)       // 65536 elements
#define TPB    256
#define GROUPS 8                // per-thread groups in filter (8*32 = 256 elem/thread)

#define TSL      8              // threshold groups per batch (>= KK, required!)
#define SLICE_E  16384          // elements per group (disjoint slices)
#define TPB_T    256

typedef unsigned long long u64;
typedef unsigned int u32;

__device__ u64 g_cand[BB * CAP];     // 8 MB scratch (static, allocation-free)
__device__ int g_count[BB];
__device__ int g_done[BB];
__device__ u32 g_tmono[BB * TSL];    // per-group maxes (monotonic encoding)

// monotonic float<->uint mapping (total order matches float compare)
__device__ __forceinline__ u32 f2mono(float f) {
    u32 b = __float_as_uint(f);
    return b ^ ((u32)((int)b >> 31) | 0x80000000u);
}
__device__ __forceinline__ float mono2f(u32 m) {
    u32 b = (m & 0x80000000u) ? (m ^ 0x80000000u) : ~m;
    return __uint_as_float(b);
}
__device__ __forceinline__ u64 make_key(float v, u32 idx) {
    return ((u64)f2mono(v) << 32) | (u32)(~idx);
}

// exact top-8 insert by key (value desc, index asc) — matches lax.top_k
__device__ __forceinline__ void consider_key(u64 (&top)[KK], u64 key) {
    if (key > top[KK - 1]) {
        top[KK - 1] = key;
        #pragma unroll
        for (int j = KK - 1; j > 0; --j) {
            if (top[j] > top[j - 1]) { u64 t = top[j]; top[j] = top[j - 1]; top[j - 1] = t; }
        }
    }
}

// ───── Pass A: per-(batch, slice) max. T = min over 8 disjoint slice maxes ───
// 8 disjoint 16K slices → 8 distinct positions all >= T → T <= true
// 8th-largest for ANY input: the filter never drops a true top-8 element.
__global__ __launch_bounds__(TPB_T)
void k_thresh(const float* __restrict__ x) {
    const int b = blockIdx.x;
    const int s = blockIdx.y;
    const int tid = threadIdx.x;
    if (s == 0 && tid == 0) { g_count[b] = 0; g_done[b] = 0; }

    const float4* __restrict__ p =
        (const float4*)(x + (size_t)b * NPB + (size_t)s * SLICE_E);
    const float NEG_INF = -__int_as_float(0x7f800000);

    float m0 = NEG_INF, m1 = NEG_INF, m2 = NEG_INF, m3 = NEG_INF;
    #pragma unroll
    for (int i = 0; i < SLICE_E / (TPB_T * 4); ++i) {   // 16 float4/thread
        float4 v = p[i * TPB_T + tid];
        m0 = fmaxf(m0, v.x); m1 = fmaxf(m1, v.y);
        m2 = fmaxf(m2, v.z); m3 = fmaxf(m3, v.w);
    }
    float m = fmaxf(fmaxf(m0, m1), fmaxf(m2, m3));

    // full-block max reduce
    #pragma unroll
    for (int off = 16; off > 0; off >>= 1)
        m = fmaxf(m, __shfl_xor_sync(0xFFFFFFFFu, m, off));
    __shared__ float wm[TPB_T / 32];
    const int lane = tid & 31, warp = tid >> 5;
    if (lane == 0) wm[warp] = m;
    __syncthreads();
    if (tid == 0) {
        float mm = wm[0];
        #pragma unroll
        for (int w = 1; w < TPB_T / 32; ++w) mm = fmaxf(mm, wm[w]);
        g_tmono[b * TSL + s] = f2mono(mm);
    }
}

// ───────────── selection (runs inside the last filter block per batch) ──────
// Reader side of the release/acquire pair: g_cand / g_count reads go through
// __ldcg (L2) so they cannot hit stale L1 lines; writers published with
// st → __threadfence → __syncthreads → atomicAdd(done).
__device__ void do_select(int b, const float* __restrict__ x,
                          float* __restrict__ out) {
    const int tid = threadIdx.x;
    const int cnt = __ldcg(&g_count[b]);

    u64 top[KK];
    #pragma unroll
    for (int j = 0; j < KK; ++j) top[j] = 0ull;

    if (cnt >= KK && cnt <= CAP) {
        for (int i = tid; i < cnt; i += TPB)
            consider_key(top, __ldcg(&g_cand[b * CAP + i]));
    } else {
        // fallback: exact brute-force scan of the whole batch (cold path)
        const float4* __restrict__ p = (const float4*)(x + (size_t)b * NPB);
        for (int i = tid; i < NPB / 4; i += TPB) {
            float4 v = p[i];
            u32 e = (u32)i * 4u;
            consider_key(top, make_key(v.x, e + 0u));
            consider_key(top, make_key(v.y, e + 1u));
            consider_key(top, make_key(v.z, e + 2u));
            consider_key(top, make_key(v.w, e + 3u));
        }
    }

    __shared__ u64 cand[TPB * KK];
    __shared__ u64 wmax[TPB / 32];
    __shared__ u64 winner;
    __shared__ u64 topk[KK];
    #pragma unroll
    for (int j = 0; j < KK; ++j) cand[tid * KK + j] = top[j];
    __syncthreads();

    const int lane = tid & 31, warp = tid >> 5;
    for (int sel = 0; sel < KK; ++sel) {
        u64 m = 0ull;
        #pragma unroll
        for (int j = 0; j < KK; ++j) { u64 cc = cand[tid * KK + j]; if (cc > m) m = cc; }
        #pragma unroll
        for (int off = 16; off > 0; off >>= 1) {
            u64 o = __shfl_down_sync(0xFFFFFFFFu, m, off);
            if (o > m) m = o;
        }
        if (lane == 0) wmax[warp] = m;
        __syncthreads();
        if (tid == 0) {
            u64 w = 0ull;
            #pragma unroll
            for (int q = 0; q < TPB / 32; ++q) if (wmax[q] > w) w = wmax[q];
            winner = w;
            topk[sel] = w;
        }
        __syncthreads();
        u64 w = winner;
        #pragma unroll
        for (int j = 0; j < KK; ++j)
            if (cand[tid * KK + j] == w) cand[tid * KK + j] = 0ull;
        __syncthreads();
    }

    float* ob = out + (size_t)b * KK * OUTC;
    for (int i = tid; i < KK * OUTC; i += TPB) ob[i] = 0.0f;
    __syncthreads();

    if (tid < KK) {
        u64 k = topk[tid];
        float val = mono2f((u32)(k >> 32));
        u32 idx = ~((u32)k);
        int ci  = (int)(idx >> 12);
        int rem = (int)(idx & 4095u);
        int y   = rem >> 6;
        int xq  = rem & 63;
        float* row = ob + tid * OUTC;
        row[ci]     = 1.0f;
        row[CC + 0] = val;
        row[CC + 1] = (float)xq * (1.0f / (WW - 1));
        row[CC + 2] = (float)y  * (1.0f / (HH - 1));
    }
}

// ───────────── Pass B: stream + filter + compact (+ fused select) ───────────
__device__ __forceinline__ void emit(int b, float v, u32 idx) {
    int s = atomicAdd(&g_count[b], 1);
    if (s < CAP) g_cand[b * CAP + s] = make_key(v, idx);
}

__global__ __launch_bounds__(TPB)
void k_filter(const float* __restrict__ x, float* __restrict__ out) {
    const int c = blockIdx.x;
    const int b = blockIdx.y;
    const int tid = threadIdx.x;

    // combine slice maxes: T = min over TSL slices (monotonic min)
    u32 tm = g_tmono[b * TSL + 0];
    #pragma unroll
    for (int s = 1; s < TSL; ++s) tm = umin(tm, g_tmono[b * TSL + s]);
    const float TF = mono2f(tm);
    const u32 TB = (tm >= 0x80000000u) ? (tm ^ 0x80000000u) : 0u;

    const u32 cbase = (u32)c * CHUNK;
    const uint4* __restrict__ p = (const uint4*)(x + (size_t)b * NPB + cbase);

    #pragma unroll 4
    for (int i = 0; i < GROUPS; ++i) {
        uint4 q[8];
        #pragma unroll
        for (int j = 0; j < 8; ++j)
            q[j] = p[(i * 8 + j) * TPB + tid];

        // per-q 4-element max (vimax3 + umax), then reduce the 8 partials.
        // Unsigned bit compare is exact for non-negative floats; negatives/NaN
        // compare high -> false positives only (rechecked exactly below).
        u32 m4[8];
        #pragma unroll
        for (int j = 0; j < 8; ++j)
            m4[j] = umax(__vimax3_u32(q[j].x, q[j].y, q[j].z), q[j].w);
        u32 r0 = __vimax3_u32(m4[0], m4[1], m4[2]);
        u32 r1 = __vimax3_u32(m4[3], m4[4], m4[5]);
        u32 r2 = __vimax3_u32(m4[6], m4[7], r0);
        u32 mm = umax(r1, r2);

        if (mm >= TB) {
            // narrowed slow path: only expand quads that can contain a survivor
            #pragma unroll
            for (int j = 0; j < 8; ++j) {
                if (m4[j] >= TB) {
                    u32 e = cbase + ((u32)(i * 8 + j) * TPB + (u32)tid) * 4u;
                    float v0f = __uint_as_float(q[j].x);
                    float v1f = __uint_as_float(q[j].y);
                    float v2f = __uint_as_float(q[j].z);
                    float v3f = __uint_as_float(q[j].w);
                    if (v0f >= TF) emit(b, v0f, e + 0u);
                    if (v1f >= TF) emit(b, v1f, e + 1u);
                    if (v2f >= TF) emit(b, v2f, e + 2u);
                    if (v3f >= TF) emit(b, v3f, e + 3u);
                }
            }
        }
    }

    // fused select, threadFenceReduction pattern:
    //   per-thread: stores → __threadfence (device-visible)
    //   __syncthreads: ALL threads' fences complete before tid0's atomic
    //   tid0: atomicAdd(done)  — the release is block-wide
    __threadfence();
    __syncthreads();
    __shared__ int is_last;
    if (tid == 0) is_last = (atomicAdd(&g_done[b], 1) == CH - 1) ? 1 : 0;
    __syncthreads();
    if (is_last) {
        __threadfence();          // acquire: order candidate reads after the
                                  // observed done-count
        do_select(b, x, out);
    }
}

extern "C" void kernel_launch(void* const* d_in, const int* in_sizes, int n_in,
                              void* d_out, int out_size) {
    const float* x = (const float*)d_in[0];
    float* out = (float*)d_out;

    dim3 gt(BB, TSL);
    k_thresh<<<gt, TPB_T>>>(x);
    dim3 gf(CH, BB);
    k_filter<<<gf, TPB>>>(x, out);
}